// round 1
// baseline (speedup 1.0000x reference)
#include <cuda_runtime.h>
#include <cuda_bf16.h>
#include <stdint.h>

// ============================================================================
// GumbelTopK: exact global k-select (radix, 12+20 bit) + elementwise gumbel
// passes. Fully graph-capturable: all control flow between phases happens on
// device via __device__ globals; kernels serialize on the capture stream.
// ============================================================================

#define N_MAX   (1u << 24)       // 4096*4096
#define H1_BINS 4096             // top 12 bits
#define H2_BINS (1u << 20)       // low 20 bits
#define TIE_CAP (1u << 20)
#define EPSF    1e-8f

__device__ unsigned int g_keys[N_MAX];
__device__ unsigned int g_hist1[H1_BINS];
__device__ unsigned int g_hist2[H2_BINS];
__device__ unsigned int g_csum2[1024];
__device__ int          g_tie_idx[TIE_CAP];
__device__ unsigned int g_tie_cnt;
__device__ unsigned int g_prefix12;
__device__ unsigned int g_k1;
__device__ unsigned int g_T;
__device__ unsigned int g_r;
__device__ int          g_cutoff;

__device__ __forceinline__ float gum(float u) {
    // -log(-log(u + eps) + eps), float32, matching reference op order
    return -logf(-logf(u + EPSF) + EPSF);
}

__device__ __forceinline__ unsigned int f2key(float f) {
    unsigned int b = __float_as_uint(f);
    // order-preserving map: ascending uint == ascending float
    return (b & 0x80000000u) ? ~b : (b | 0x80000000u);
}

// ---------------------------------------------------------------------------
// reset: zero histograms + tie counter (must happen every graph replay)
// ---------------------------------------------------------------------------
__global__ void reset_k() {
    int stride = gridDim.x * blockDim.x;
    for (unsigned int i = blockIdx.x * blockDim.x + threadIdx.x; i < H2_BINS; i += stride)
        g_hist2[i] = 0;
    unsigned int t = blockIdx.x * blockDim.x + threadIdx.x;
    if (t < H1_BINS) g_hist1[t] = 0;
    if (t == 0) g_tie_cnt = 0;
}

// ---------------------------------------------------------------------------
// pass A: score + key store + 12-bit histogram (smem privatized)
// ---------------------------------------------------------------------------
__global__ void score_hist_k(const float* __restrict__ logits,
                             const float* __restrict__ u1,
                             const int* __restrict__ training, int n4) {
    __shared__ unsigned int sh[H1_BINS];
    for (int i = threadIdx.x; i < H1_BINS; i += blockDim.x) sh[i] = 0;
    __syncthreads();
    const int tr = *training;
    const int stride = gridDim.x * blockDim.x;
    for (int i = blockIdx.x * blockDim.x + threadIdx.x; i < n4; i += stride) {
        float4 l = ((const float4*)logits)[i];
        float4 u = ((const float4*)u1)[i];
        float s0 = tr ? (l.x + gum(u.x)) : l.x;
        float s1 = tr ? (l.y + gum(u.y)) : l.y;
        float s2 = tr ? (l.z + gum(u.z)) : l.z;
        float s3 = tr ? (l.w + gum(u.w)) : l.w;
        uint4 kk;
        kk.x = f2key(s0); kk.y = f2key(s1); kk.z = f2key(s2); kk.w = f2key(s3);
        ((uint4*)g_keys)[i] = kk;
        atomicAdd(&sh[kk.x >> 20], 1u);
        atomicAdd(&sh[kk.y >> 20], 1u);
        atomicAdd(&sh[kk.z >> 20], 1u);
        atomicAdd(&sh[kk.w >> 20], 1u);
    }
    __syncthreads();
    for (int i = threadIdx.x; i < H1_BINS; i += blockDim.x) {
        unsigned int c = sh[i];
        if (c) atomicAdd(&g_hist1[i], c);
    }
}

// ---------------------------------------------------------------------------
// block-wide inclusive scan helper (blockDim.x entries in smem)
// ---------------------------------------------------------------------------
__device__ __forceinline__ unsigned int block_incl_scan(unsigned int v, unsigned int* sh) {
    int t = threadIdx.x;
    sh[t] = v;
    __syncthreads();
    for (int off = 1; off < blockDim.x; off <<= 1) {
        unsigned int add = (t >= off) ? sh[t - off] : 0u;
        __syncthreads();
        sh[t] += add;
        __syncthreads();
    }
    return sh[t];
}

// ---------------------------------------------------------------------------
// select level 1: find 12-bit bin holding rank-k (descending) and rank within
// ---------------------------------------------------------------------------
__global__ void select1_k(const int* __restrict__ kp) {
    __shared__ unsigned int sh[1024];
    const unsigned int k = (unsigned int)(*kp);
    int t = threadIdx.x;  // 1024 threads, 4 descending bins each
    unsigned int c[4], s = 0;
#pragma unroll
    for (int j = 0; j < 4; j++) { c[j] = g_hist1[4095 - (4 * t + j)]; s += c[j]; }
    unsigned int incl = block_incl_scan(s, sh);
    unsigned int excl = incl - s;
    if (excl < k && k <= incl) {
        unsigned int cum = excl;
#pragma unroll
        for (int j = 0; j < 4; j++) {
            if (cum + c[j] >= k) { g_prefix12 = 4095 - (4 * t + j); g_k1 = k - cum; break; }
            cum += c[j];
        }
    }
}

// ---------------------------------------------------------------------------
// pass B: 20-bit histogram inside selected 12-bit bin
// ---------------------------------------------------------------------------
__global__ void hist2_k(int n4) {
    const unsigned int pfx = g_prefix12;
    const int stride = gridDim.x * blockDim.x;
    for (int i = blockIdx.x * blockDim.x + threadIdx.x; i < n4; i += stride) {
        uint4 kk = ((const uint4*)g_keys)[i];
        if ((kk.x >> 20) == pfx) atomicAdd(&g_hist2[kk.x & 0xFFFFFu], 1u);
        if ((kk.y >> 20) == pfx) atomicAdd(&g_hist2[kk.y & 0xFFFFFu], 1u);
        if ((kk.z >> 20) == pfx) atomicAdd(&g_hist2[kk.z & 0xFFFFFu], 1u);
        if ((kk.w >> 20) == pfx) atomicAdd(&g_hist2[kk.w & 0xFFFFFu], 1u);
    }
}

// chunk sums of hist2 (1024 chunks of 1024 bins), coalesced
__global__ void chunksum2_k() {
    __shared__ unsigned int sh[256];
    int b = blockIdx.x;
    unsigned int s = 0;
    for (int j = threadIdx.x; j < 1024; j += 256) s += g_hist2[b * 1024 + j];
    sh[threadIdx.x] = s;
    __syncthreads();
    for (int off = 128; off > 0; off >>= 1) {
        if (threadIdx.x < off) sh[threadIdx.x] += sh[threadIdx.x + off];
        __syncthreads();
    }
    if (threadIdx.x == 0) g_csum2[b] = sh[0];
}

// select level 2: exact threshold key T and r = #(==T) to include
__global__ void select2_k() {
    __shared__ unsigned int sh[1024];
    __shared__ unsigned int s_chunk, s_k2;
    int t = threadIdx.x;
    const unsigned int k1 = g_k1;
    unsigned int s = g_csum2[1023 - t];  // descending chunk order
    unsigned int incl = block_incl_scan(s, sh);
    unsigned int excl = incl - s;
    if (excl < k1 && k1 <= incl) { s_chunk = 1023 - t; s_k2 = k1 - excl; }
    __syncthreads();
    const unsigned int a = s_chunk;
    const unsigned int k2 = s_k2;
    // within ascending chunk a, descending bin for thread t:
    unsigned int bin = a * 1024 + 1023 - t;
    unsigned int cb = g_hist2[bin];
    __syncthreads();
    unsigned int incl2 = block_incl_scan(cb, sh);
    unsigned int excl2 = incl2 - cb;
    if (excl2 < k2 && k2 <= incl2) {
        g_T = (g_prefix12 << 20) | bin;
        g_r = k2 - excl2;
    }
}

// ---------------------------------------------------------------------------
// pass C: collect indices of elements == T
// ---------------------------------------------------------------------------
__global__ void collect_k(int n4) {
    const unsigned int T = g_T;
    const int stride = gridDim.x * blockDim.x;
    for (int i = blockIdx.x * blockDim.x + threadIdx.x; i < n4; i += stride) {
        uint4 kk = ((const uint4*)g_keys)[i];
        if (kk.x == T) { unsigned int p = atomicAdd(&g_tie_cnt, 1u); if (p < TIE_CAP) g_tie_idx[p] = 4 * i + 0; }
        if (kk.y == T) { unsigned int p = atomicAdd(&g_tie_cnt, 1u); if (p < TIE_CAP) g_tie_idx[p] = 4 * i + 1; }
        if (kk.z == T) { unsigned int p = atomicAdd(&g_tie_cnt, 1u); if (p < TIE_CAP) g_tie_idx[p] = 4 * i + 2; }
        if (kk.w == T) { unsigned int p = atomicAdd(&g_tie_cnt, 1u); if (p < TIE_CAP) g_tie_idx[p] = 4 * i + 3; }
    }
}

// find r-th smallest tie index -> cutoff (ties with idx <= cutoff are in-mask)
__global__ void select_idx_k(int n) {
    __shared__ int s_cnt;
    unsigned int m = g_tie_cnt;
    if (m > TIE_CAP) m = TIE_CAP;
    const unsigned int r = g_r;
    if (r >= m) { if (threadIdx.x == 0) g_cutoff = 0x7FFFFFFF; return; }
    int lo = 0, hi = n - 1;
    while (lo < hi) {
        int mid = lo + (hi - lo) / 2;
        if (threadIdx.x == 0) s_cnt = 0;
        __syncthreads();
        int c = 0;
        for (unsigned int j = threadIdx.x; j < m; j += blockDim.x)
            if (g_tie_idx[j] <= mid) c++;
        atomicAdd(&s_cnt, c);
        __syncthreads();
        if (s_cnt >= (int)r) hi = mid; else lo = mid + 1;
        __syncthreads();
    }
    if (threadIdx.x == 0) g_cutoff = lo;
}

// ---------------------------------------------------------------------------
// pass D: final output
// ---------------------------------------------------------------------------
__device__ __forceinline__ float out_elem(unsigned int key, int idx, float u0, float u1,
                                          unsigned int T, int cutoff, int tr) {
    float m = (key > T || (key == T && idx <= cutoff)) ? 1.0f : 0.0f;
    if (!tr) return m;
    float g0 = gum(u0);
    float g1 = gum(u1);
    return (m + g1 > g0) ? 1.0f : 0.0f;
}

__global__ void final_k(const float* __restrict__ u2,
                        const int* __restrict__ training,
                        float* __restrict__ out, int n4) {
    const unsigned int T = g_T;
    const int cutoff = g_cutoff;
    const int tr = *training;
    const int stride = gridDim.x * blockDim.x;
    for (int i = blockIdx.x * blockDim.x + threadIdx.x; i < n4; i += stride) {
        uint4 kk = ((const uint4*)g_keys)[i];
        float4 a = ((const float4*)u2)[2 * i];
        float4 b = ((const float4*)u2)[2 * i + 1];
        float4 o;
        o.x = out_elem(kk.x, 4 * i + 0, a.x, a.y, T, cutoff, tr);
        o.y = out_elem(kk.y, 4 * i + 1, a.z, a.w, T, cutoff, tr);
        o.z = out_elem(kk.z, 4 * i + 2, b.x, b.y, T, cutoff, tr);
        o.w = out_elem(kk.w, 4 * i + 3, b.z, b.w, T, cutoff, tr);
        ((float4*)out)[i] = o;
    }
}

// ---------------------------------------------------------------------------
extern "C" void kernel_launch(void* const* d_in, const int* in_sizes, int n_in,
                              void* d_out, int out_size) {
    const float* mask_logits = (const float*)d_in[0];
    const float* u1          = (const float*)d_in[1];
    const float* u2          = (const float*)d_in[2];
    const int*   kp          = (const int*)d_in[3];
    const int*   training    = (const int*)d_in[4];
    float* out = (float*)d_out;

    const int n  = in_sizes[0];
    const int n4 = n / 4;

    reset_k<<<2048, 512>>>();
    score_hist_k<<<1024, 512>>>(mask_logits, u1, training, n4);
    select1_k<<<1, 1024>>>(kp);
    hist2_k<<<2048, 256>>>(n4);
    chunksum2_k<<<1024, 256>>>();
    select2_k<<<1, 1024>>>();
    collect_k<<<2048, 256>>>(n4);
    select_idx_k<<<1, 1024>>>(n);
    final_k<<<2048, 256>>>(u2, training, out, n4);
}